// round 1
// baseline (speedup 1.0000x reference)
#include <cuda_runtime.h>
#include <cstdint>

#define B_   8
#define N_   16384
#define DIM_ 192
#define RC_  16
#define M_   64

// ---- device scratch (statics, no allocation) ----
__device__ float g_vraw[B_ * M_ * DIM_];
__device__ float g_v[B_ * M_ * DIM_];
__device__ float g_k[B_ * M_ * RC_];

// ============================================================
// Kernel 1: v_raw = dict @ wv_w + wv_b      (512 blocks x 192 thr)
// ============================================================
__global__ void k_vraw(const float* __restrict__ dict,
                       const float* __restrict__ wv_w,
                       const float* __restrict__ wv_b) {
    __shared__ float ds[DIM_];
    int bm = blockIdx.x;
    int c  = threadIdx.x;
    ds[c] = dict[bm * DIM_ + c];
    __syncthreads();
    float acc = wv_b[c];
#pragma unroll 8
    for (int d = 0; d < DIM_; d++)
        acc += ds[d] * wv_w[d * DIM_ + c];
    g_vraw[bm * DIM_ + c] = acc;
}

// ============================================================
// Kernel 2: depthwise conv (3x3 kernel, width-1 image -> center col) + bias + exact GELU
// ============================================================
__global__ void k_conv(const float* __restrict__ conv_w,
                       const float* __restrict__ conv_b) {
    int bm = blockIdx.x;
    int c  = threadIdx.x;
    int m  = bm & (M_ - 1);
    // conv_w layout (C,1,3,3); only center column (index 1) touches valid width
    float w0 = conv_w[c * 9 + 1];
    float w1 = conv_w[c * 9 + 4];
    float w2 = conv_w[c * 9 + 7];
    float acc = conv_b[c] + w1 * g_vraw[bm * DIM_ + c];
    if (m > 0)      acc += w0 * g_vraw[(bm - 1) * DIM_ + c];
    if (m < M_ - 1) acc += w2 * g_vraw[(bm + 1) * DIM_ + c];
    // exact gelu: 0.5*x*(1+erf(x/sqrt(2)))
    float g = 0.5f * acc * (1.0f + erff(acc * 0.70710678118654752440f));
    g_v[bm * DIM_ + c] = g;
}

// ============================================================
// Kernel 3: k = l2norm(layernorm(dict @ wk_w + wk_b))   (512 blocks x 32 thr)
// ============================================================
__global__ void k_kproj(const float* __restrict__ dict,
                        const float* __restrict__ wk_w,
                        const float* __restrict__ wk_b,
                        const float* __restrict__ kn_g,
                        const float* __restrict__ kn_b) {
    int bm   = blockIdx.x;
    int lane = threadIdx.x;
    int r    = lane & 15;
    const float* drow = dict + bm * DIM_;
    float acc = wk_b[r];
#pragma unroll 8
    for (int d = 0; d < DIM_; d++)
        acc += drow[d] * wk_w[d * RC_ + r];
    // layernorm over 16
    float s = acc;
    for (int o = 8; o; o >>= 1) s += __shfl_xor_sync(0xffffffffu, s, o);
    float mu = s * 0.0625f;
    float dv = acc - mu;
    float vs = dv * dv;
    for (int o = 8; o; o >>= 1) vs += __shfl_xor_sync(0xffffffffu, vs, o);
    float qn = dv * rsqrtf(vs * 0.0625f + 1e-5f) * kn_g[r] + kn_b[r];
    // l2 norm
    float n2 = qn * qn;
    for (int o = 8; o; o >>= 1) n2 += __shfl_xor_sync(0xffffffffu, n2, o);
    qn = qn / fmaxf(sqrtf(n2), 1e-12f);
    if (lane < 16) g_k[bm * RC_ + r] = qn;
}

// ============================================================
// Main fused kernel: qproj + LN + L2 + logits + softmax + attn@v
//   block = 256 thr (8 warps), 64 tokens/block; warp = 8 tokens
// ============================================================
// smem float offsets
#define SM_VS   0          // 64*192        = 12288
#define SM_WQ   12288      // 48*16 float4  =  3072 floats
#define SM_QNT  15360      // 16*65         =  1040
#define SM_ATT  16400      // 64*68         =  4352
#define SM_XS   20752      // 8*2*196       =  3136
#define SM_TOT  23888      // floats -> 95552 bytes

__device__ __forceinline__ unsigned long long pack2f(float a, float b) {
    unsigned long long r;
    asm("mov.b64 %0, {%1, %2};" : "=l"(r) : "f"(a), "f"(b));
    return r;
}
__device__ __forceinline__ unsigned long long ffma2(unsigned long long a,
                                                    unsigned long long b,
                                                    unsigned long long c) {
    unsigned long long d;
    asm("fma.rn.f32x2 %0, %1, %2, %3;" : "=l"(d) : "l"(a), "l"(b), "l"(c));
    return d;
}

__global__ void __launch_bounds__(256, 2) k_main(
    const float* __restrict__ x,
    const float* __restrict__ wq_w,
    const float* __restrict__ wq_b,
    const float* __restrict__ qn_g,
    const float* __restrict__ qn_b,
    const float* __restrict__ temperature,
    float* __restrict__ out,
    float* __restrict__ attn) {
    extern __shared__ float sm[];
    int tid  = threadIdx.x;
    int lane = tid & 31;
    int w    = tid >> 5;
    int b       = blockIdx.x >> 8;
    int tokBase = (blockIdx.x & 255) << 6;

    // stage v tile (64x192) to smem
    {
        const float4* src = (const float4*)(g_v + b * (M_ * DIM_));
        float4* dst = (float4*)sm;
        for (int i = tid; i < 3072; i += 256) dst[i] = src[i];
    }
    // stage wq transposed into float4 rows: wq4[d4*16 + r] = wq[4d4..4d4+3][r]
    for (int i = tid; i < DIM_ * RC_; i += 256) {
        int d = i >> 4, r = i & 15;
        sm[SM_WQ + (((d >> 2) * 16 + r) << 2) + (d & 3)] = wq_w[i];
    }
    __syncthreads();

    // k rows in registers: lane <-> m and m+32
    float kreg0[16], kreg1[16];
#pragma unroll
    for (int r = 0; r < 16; r++) {
        kreg0[r] = g_k[(b * M_ + lane) * RC_ + r];
        kreg1[r] = g_k[(b * M_ + 32 + lane) * RC_ + r];
    }
    float invT = 1.0f / fmaxf(temperature[0], 0.5f);
    int h = lane >> 4, r = lane & 15;
    float gq = qn_g[r], bq = qn_b[r], bwq = wq_b[r];

    // ---------------- stage 1: q / logits / softmax, 2 tokens per pass ----------------
    for (int p = 0; p < 4; p++) {
        int t0 = (w << 3) + (p << 1);  // block-local token index of pair base
        const float* xsrc = x + ((size_t)(b * N_ + tokBase + t0)) * DIM_;
        float* xsl = sm + SM_XS + w * 392;  // 2 rows, stride 196 (bank-pad)
#pragma unroll
        for (int i = 0; i < 3; i++) {
            int idx = lane + (i << 5);          // float4 index 0..95
            float4 v4 = ((const float4*)xsrc)[idx];
            int row = idx / 48, col = idx % 48;
            *((float4*)(xsl + row * 196 + (col << 2))) = v4;
        }
        __syncwarp();
        // qproj: lane = 16h + r computes q[r] of token t0+h
        float acc = bwq;
        const float4* xrow = (const float4*)(xsl + h * 196);
        const float4* wq4p = (const float4*)(sm + SM_WQ);
#pragma unroll
        for (int d4 = 0; d4 < 48; d4++) {
            float4 xv = xrow[d4];
            float4 wv = wq4p[(d4 << 4) + r];
            acc += xv.x * wv.x;
            acc += xv.y * wv.y;
            acc += xv.z * wv.z;
            acc += xv.w * wv.w;
        }
        // layernorm over 16 (half-warp butterfly)
        float s = acc;
        for (int o = 8; o; o >>= 1) s += __shfl_xor_sync(0xffffffffu, s, o);
        float mu = s * 0.0625f;
        float dv = acc - mu;
        float vv = dv * dv;
        for (int o = 8; o; o >>= 1) vv += __shfl_xor_sync(0xffffffffu, vv, o);
        float qn = dv * rsqrtf(vv * 0.0625f + 1e-5f) * gq + bq;
        float n2 = qn * qn;
        for (int o = 8; o; o >>= 1) n2 += __shfl_xor_sync(0xffffffffu, n2, o);
        qn = qn / fmaxf(sqrtf(n2), 1e-12f);
        sm[SM_QNT + r * 65 + t0 + h] = qn;
        __syncwarp();

        // logits + softmax, full warp per token; lane <-> {m, m+32}
#pragma unroll
        for (int hh = 0; hh < 2; hh++) {
            int tt = t0 + hh;
            float l0 = 0.f, l1 = 0.f;
#pragma unroll
            for (int rr = 0; rr < 16; rr++) {
                float qv = sm[SM_QNT + rr * 65 + tt];
                l0 += qv * kreg0[rr];
                l1 += qv * kreg1[rr];
            }
            l0 *= invT;
            l1 *= invT;
            float mx = fmaxf(l0, l1);
            for (int o = 16; o; o >>= 1) mx = fmaxf(mx, __shfl_xor_sync(0xffffffffu, mx, o));
            float e0 = __expf(l0 - mx), e1 = __expf(l1 - mx);
            float es = e0 + e1;
            for (int o = 16; o; o >>= 1) es += __shfl_xor_sync(0xffffffffu, es, o);
            float inv = 1.0f / es;
            float a0 = e0 * inv, a1 = e1 * inv;
            float* ap = attn + ((size_t)(b * N_ + tokBase + tt)) * M_;
            ap[lane]      = a0;
            ap[lane + 32] = a1;
            sm[SM_ATT + lane * 68 + tt]        = a0;  // transposed tile, stride 68
            sm[SM_ATT + (lane + 32) * 68 + tt] = a1;
        }
    }
    __syncwarp();

    // ---------------- stage 2: out = attn @ v via packed FFMA2, 8 tokens/warp ----------------
    unsigned long long acc2[8][3];
#pragma unroll
    for (int t = 0; t < 8; t++)
#pragma unroll
        for (int j = 0; j < 3; j++) acc2[t][j] = 0ull;

    const float2* v2 = (const float2*)sm;  // v as float2[64][96]
#pragma unroll 2
    for (int m = 0; m < M_; m++) {
        const float4* arow = (const float4*)(sm + SM_ATT + m * 68 + (w << 3));
        float4 aA = arow[0];
        float4 aB = arow[1];
        float2 va = v2[m * 96 + lane];
        float2 vb = v2[m * 96 + 32 + lane];
        float2 vc = v2[m * 96 + 64 + lane];
        unsigned long long bva = pack2f(va.x, va.y);
        unsigned long long bvb = pack2f(vb.x, vb.y);
        unsigned long long bvc = pack2f(vc.x, vc.y);
        float at[8] = {aA.x, aA.y, aA.z, aA.w, aB.x, aB.y, aB.z, aB.w};
#pragma unroll
        for (int t = 0; t < 8; t++) {
            unsigned long long am = pack2f(at[t], at[t]);
            acc2[t][0] = ffma2(bva, am, acc2[t][0]);
            acc2[t][1] = ffma2(bvb, am, acc2[t][1]);
            acc2[t][2] = ffma2(bvc, am, acc2[t][2]);
        }
    }
#pragma unroll
    for (int t = 0; t < 8; t++) {
        float* orow = out + ((size_t)(b * N_ + tokBase + (w << 3) + t)) * DIM_;
#pragma unroll
        for (int j = 0; j < 3; j++) {
            float rx, ry;
            asm("mov.b64 {%0, %1}, %2;" : "=f"(rx), "=f"(ry) : "l"(acc2[t][j]));
            float2 rv = {rx, ry};
            ((float2*)orow)[(j << 5) + lane] = rv;
        }
    }
}

// ============================================================
extern "C" void kernel_launch(void* const* d_in, const int* in_sizes, int n_in,
                              void* d_out, int out_size) {
    const float* x    = (const float*)d_in[0];
    const float* dict = (const float*)d_in[1];
    // H/W may or may not appear as scalar int inputs; detect by size
    int base = (in_sizes[2] == 1 && in_sizes[3] == 1) ? 4 : 2;
    const float* wq_w = (const float*)d_in[base + 0];
    const float* wq_b = (const float*)d_in[base + 1];
    const float* wk_w = (const float*)d_in[base + 2];
    const float* wk_b = (const float*)d_in[base + 3];
    const float* wv_w = (const float*)d_in[base + 4];
    const float* wv_b = (const float*)d_in[base + 5];
    const float* qn_g = (const float*)d_in[base + 6];
    const float* qn_b = (const float*)d_in[base + 7];
    const float* kn_g = (const float*)d_in[base + 8];
    const float* kn_b = (const float*)d_in[base + 9];
    const float* cv_w = (const float*)d_in[base + 10];
    const float* cv_b = (const float*)d_in[base + 11];
    const float* temp = (const float*)d_in[base + 12];

    float* out  = (float*)d_out;
    // tuple output (out, attn): attn occupies the trailing B*N*M floats
    float* attn = out + ((size_t)out_size - (size_t)B_ * N_ * M_);

    k_vraw<<<B_ * M_, DIM_>>>(dict, wv_w, wv_b);
    k_conv<<<B_ * M_, DIM_>>>(cv_w, cv_b);
    k_kproj<<<B_ * M_, 32>>>(dict, wk_w, wk_b, kn_g, kn_b);

    cudaFuncSetAttribute(k_main, cudaFuncAttributeMaxDynamicSharedMemorySize,
                         SM_TOT * (int)sizeof(float));
    k_main<<<B_ * (N_ / 64), 256, SM_TOT * sizeof(float)>>>(
        x, wq_w, wq_b, qn_g, qn_b, temp, out, attn);
}